// round 13
// baseline (speedup 1.0000x reference)
#include <cuda_runtime.h>

// 4 pyramids -> bilinear-resize to 256x256 (half-pixel, clamp-to-edge) ->
// gather 4096 flat indices -> concat channels. out [4, 960, 4096] fp32.
//
// R11 ncu: k_f3 = 20.4us, occ=34%, LDS-bound (16 scalar LDS per index).
// R12: channel-interleaved smem (float4 for f3, float2 for f2) -> one wide
// LDS per tap covers all channels (4x fewer LDS instrs), plus index-split
// grids for occupancy. f0 gets smaller CPT for more resident warps.

#define NIDX 4096
#define TPB  256

// Bilinear geometry on source grid S; offsets in units of pitch P elements.
template <int S, int P>
__device__ __forceinline__ void geom(int idx, int& o00, int& o01, int& o10, int& o11,
                                     float& w00, float& w01, float& w10, float& w11)
{
    const int y = idx >> 8;
    const int x = idx & 255;
    constexpr float scale = (float)S * (1.0f / 256.0f);
    const float fy = ((float)y + 0.5f) * scale - 0.5f;
    const float fx = ((float)x + 0.5f) * scale - 0.5f;
    const float fy0 = floorf(fy);
    const float fx0 = floorf(fx);
    const float wy = fy - fy0;
    const float wx = fx - fx0;
    const int iy0 = (int)fy0, ix0 = (int)fx0;
    const int y0 = min(max(iy0, 0), S - 1);
    const int y1 = min(max(iy0 + 1, 0), S - 1);
    const int x0 = min(max(ix0, 0), S - 1);
    const int x1 = min(max(ix0 + 1, 0), S - 1);
    o00 = y0 * P + x0;  o01 = y0 * P + x1;
    o10 = y1 * P + x0;  o11 = y1 * P + x1;
    w00 = (1.0f - wy) * (1.0f - wx);
    w01 = (1.0f - wy) * wx;
    w10 = wy * (1.0f - wx);
    w11 = wy * wx;
}

// ---------------- f0: identity gather (scale 1), 4 ch/thread ----------------
#define CPT0 4
__global__ __launch_bounds__(TPB) void k_f0(
    const float* __restrict__ f0, const int* __restrict__ indices,
    float* __restrict__ out)
{
    const int i = blockIdx.x * TPB + threadIdx.x;
    const int g = blockIdx.y;            // 16 groups of 4 channels
    const int b = blockIdx.z;
    const int idx = __ldg(indices + i);
    const float* base = f0 + ((size_t)(b * 64 + g * CPT0) << 16);
    float* ob = out + ((size_t)b * 960 + g * CPT0) * NIDX + i;
    #pragma unroll
    for (int k = 0; k < CPT0; k++)
        ob[(size_t)k * NIDX] = __ldg(base + ((size_t)k << 16) + idx);
}

// ---------------- f1: S=128, 1 channel per block, smem 128x132 ----------------
#define P1 132
__global__ __launch_bounds__(TPB) void k_f1(
    const float* __restrict__ f1, const int* __restrict__ indices,
    float* __restrict__ out)
{
    extern __shared__ float sm[];                 // 128 * 132 floats
    const int c = blockIdx.x;                     // 0..127
    const int b = blockIdx.y;
    const int t = threadIdx.x;

    const float4* p4 = (const float4*)(f1 + ((size_t)(b * 128 + c) << 14));
    #pragma unroll
    for (int k = 0; k < 16; k++) {                // 4096 float4 / 256 thr
        const int j4 = t + k * TPB;
        float4 v = __ldg(p4 + j4);
        const int y = j4 >> 5;                    // 32 float4 per row
        const int xq = j4 & 31;
        *(float4*)&sm[y * P1 + xq * 4] = v;
    }
    __syncthreads();

    float* ob = out + ((size_t)b * 960 + 64 + c) * NIDX;
    #pragma unroll 4
    for (int k = 0; k < 16; k++) {
        const int i = t + k * TPB;
        const int idx = __ldg(indices + i);
        int o00, o01, o10, o11; float w00, w01, w10, w11;
        geom<128, P1>(idx, o00, o01, o10, o11, w00, w01, w10, w11);
        ob[i] = sm[o00] * w00 + sm[o01] * w01 + sm[o10] * w10 + sm[o11] * w11;
    }
}

// ------- f2: S=64, 2 channels interleaved as float2, pitch 66 f2-units -------
#define P2 66
__global__ __launch_bounds__(TPB) void k_f2(
    const float* __restrict__ f2, const int* __restrict__ indices,
    float* __restrict__ out)
{
    __shared__ float2 sm[64 * P2];                 // 33792 B
    float* smf = (float*)sm;
    const int g = blockIdx.x;                      // 0..127 channel pairs
    const int b = blockIdx.y;
    const int ch = blockIdx.z;                     // index chunk 0..1
    const int t = threadIdx.x;

    const float* base = f2 + ((size_t)(b * 256 + g * 2) << 12);
    #pragma unroll
    for (int cc = 0; cc < 2; cc++) {
        const float4* p4 = (const float4*)(base + ((size_t)cc << 12));
        #pragma unroll
        for (int k = 0; k < 4; k++) {              // 1024 float4 per plane
            const int j4 = t + k * TPB;
            float4 v = __ldg(p4 + j4);
            const int y = j4 >> 4;                 // 16 float4 per row
            const int x0 = (j4 & 15) * 4;
            const int e = y * P2 + x0;             // float2 element index
            smf[(e + 0) * 2 + cc] = v.x;
            smf[(e + 1) * 2 + cc] = v.y;
            smf[(e + 2) * 2 + cc] = v.z;
            smf[(e + 3) * 2 + cc] = v.w;
        }
    }
    __syncthreads();

    float* ob = out + ((size_t)b * 960 + 192 + g * 2) * NIDX;
    #pragma unroll 4
    for (int k = 0; k < 8; k++) {                  // 2048 indices per chunk
        const int i = ch * 2048 + t + k * TPB;
        const int idx = __ldg(indices + i);
        int o00, o01, o10, o11; float w00, w01, w10, w11;
        geom<64, P2>(idx, o00, o01, o10, o11, w00, w01, w10, w11);
        const float2 v00 = sm[o00], v01 = sm[o01], v10 = sm[o10], v11 = sm[o11];
        ob[i]        = v00.x * w00 + v01.x * w01 + v10.x * w10 + v11.x * w11;
        ob[NIDX + i] = v00.y * w00 + v01.y * w01 + v10.y * w10 + v11.y * w11;
    }
}

// ------- f3: S=32, 4 channels interleaved as float4, pitch 34 f4-units -------
#define P3 34
__global__ __launch_bounds__(TPB) void k_f3(
    const float* __restrict__ f3, const int* __restrict__ indices,
    float* __restrict__ out)
{
    __shared__ float4 sm[32 * P3];                 // 17408 B
    float* smf = (float*)sm;
    const int g = blockIdx.x;                      // 0..127 channel quads
    const int b = blockIdx.y;
    const int ch = blockIdx.z;                     // index chunk 0..3
    const int t = threadIdx.x;

    const float* base = f3 + ((size_t)(b * 512 + g * 4) << 10);
    #pragma unroll
    for (int cc = 0; cc < 4; cc++) {
        const float4* p4 = (const float4*)(base + ((size_t)cc << 10));
        const int j4 = t;                          // 256 float4 per plane
        float4 v = __ldg(p4 + j4);
        const int y = j4 >> 3;                     // 8 float4 per row
        const int x0 = (j4 & 7) * 4;
        const int e = y * P3 + x0;                 // float4 element index
        smf[(e + 0) * 4 + cc] = v.x;
        smf[(e + 1) * 4 + cc] = v.y;
        smf[(e + 2) * 4 + cc] = v.z;
        smf[(e + 3) * 4 + cc] = v.w;
    }
    __syncthreads();

    float* ob = out + ((size_t)b * 960 + 448 + g * 4) * NIDX;
    #pragma unroll 4
    for (int k = 0; k < 4; k++) {                  // 1024 indices per chunk
        const int i = ch * 1024 + t + k * TPB;
        const int idx = __ldg(indices + i);
        int o00, o01, o10, o11; float w00, w01, w10, w11;
        geom<32, P3>(idx, o00, o01, o10, o11, w00, w01, w10, w11);
        const float4 v00 = sm[o00], v01 = sm[o01], v10 = sm[o10], v11 = sm[o11];
        ob[i]            = v00.x * w00 + v01.x * w01 + v10.x * w10 + v11.x * w11;
        ob[NIDX + i]     = v00.y * w00 + v01.y * w01 + v10.y * w10 + v11.y * w11;
        ob[2 * NIDX + i] = v00.z * w00 + v01.z * w01 + v10.z * w10 + v11.z * w11;
        ob[3 * NIDX + i] = v00.w * w00 + v01.w * w01 + v10.w * w10 + v11.w * w11;
    }
}

extern "C" void kernel_launch(void* const* d_in, const int* in_sizes, int n_in,
                              void* d_out, int out_size)
{
    const float* f0 = (const float*)d_in[0];
    const float* f1 = (const float*)d_in[1];
    const float* f2 = (const float*)d_in[2];
    const float* f3 = (const float*)d_in[3];
    const int* indices = (const int*)d_in[4];
    float* out = (float*)d_out;

    const int smem1 = 128 * P1 * (int)sizeof(float);   // 67584 B > 48KB opt-in
    cudaFuncSetAttribute(k_f1, cudaFuncAttributeMaxDynamicSharedMemorySize, smem1);

    k_f0<<<dim3(NIDX / TPB, 16, 4), TPB>>>(f0, indices, out);     // 1024 blocks
    k_f1<<<dim3(128, 4), TPB, smem1>>>(f1, indices, out);         // 512 blocks
    k_f2<<<dim3(128, 4, 2), TPB>>>(f2, indices, out);             // 1024 blocks
    k_f3<<<dim3(128, 4, 4), TPB>>>(f3, indices, out);             // 2048 blocks
}